// round 3
// baseline (speedup 1.0000x reference)
#include <cuda_runtime.h>

// Problem constants
#define B_   32
#define C_   2048
#define D_   16
#define M_   784           // 28*28
#define CHUNK  256
#define NCHUNK (C_/CHUNK)  // 8
#define EPS  1e-5f

// ---------------- scratch (device globals; no allocations) ----------------
__device__ float g_Y[B_ * D_ * M_];     // conv output, pre-BN  (1.6 MB)
__device__ float g_bnS[D_];             // BN1 fused scale
__device__ float g_bnB[D_];             // BN1 fused bias
__device__ float g_cov[B_ * D_ * D_];   // covariance pool
__device__ float g_r[B_ * 64];          // row-conv output

// packed f32x2 FMA (Blackwell): acc = a*b + acc, lanewise on 2 packed floats
__device__ __forceinline__ void fma2(unsigned long long &acc,
                                     unsigned long long a,
                                     unsigned long long b) {
    asm("fma.rn.f32x2 %0, %1, %2, %0;" : "+l"(acc) : "l"(a), "l"(b));
}

// ---------------- kZ: zero the Y accumulator ----------------
__global__ void kZ() {
    int i = blockIdx.x * blockDim.x + threadIdx.x;
    if (i < B_ * D_ * M_) g_Y[i] = 0.0f;
}

// ---------------- kA: y[b,d,m] += sum_{c in chunk} w[d,c] * x[b,c,m] -------
// grid = B_*NCHUNK blocks, 416 threads (392 active compute lanes, 2 m each)
__global__ __launch_bounds__(416) void kA(const float* __restrict__ x,
                                          const float* __restrict__ w) {
    __shared__ __align__(16) float2 sw[CHUNK][D_];  // (w,w) duplicated pairs, 32KB

    const int b   = blockIdx.x / NCHUNK;
    const int ch  = blockIdx.x % NCHUNK;
    const int c0  = ch * CHUNK;
    const int tid = threadIdx.x;

    // stage W chunk to shared, duplicated into both halves for f32x2
    for (int i = tid; i < CHUNK * D_; i += 416) {
        int c = i >> 4, d = i & 15;
        float wv = w[d * C_ + c0 + c];
        sw[c][d] = make_float2(wv, wv);
    }
    __syncthreads();

    if (tid >= 392) return;             // 392*2 = 784 m positions
    const int m0 = tid * 2;

    const float* xb = x + ((size_t)b * C_ + c0) * M_ + m0;

    unsigned long long acc[D_];
#pragma unroll
    for (int d = 0; d < D_; d++) acc[d] = 0ull;

#pragma unroll 2
    for (int c = 0; c < CHUNK; c++) {
        unsigned long long xv =
            *reinterpret_cast<const unsigned long long*>(xb + (size_t)c * M_);
        const ulonglong2* wp = reinterpret_cast<const ulonglong2*>(&sw[c][0]);
#pragma unroll
        for (int q = 0; q < 8; q++) {
            ulonglong2 w2 = wp[q];
            fma2(acc[2 * q],     xv, w2.x);
            fma2(acc[2 * q + 1], xv, w2.y);
        }
    }

    float* yb = g_Y + (b * D_) * M_ + m0;
#pragma unroll
    for (int d = 0; d < D_; d++) {
        float lo = __uint_as_float((unsigned int)(acc[d] & 0xffffffffull));
        float hi = __uint_as_float((unsigned int)(acc[d] >> 32));
        atomicAdd(yb + d * M_,     lo);
        atomicAdd(yb + d * M_ + 1, hi);
    }
}

// ---------------- kB: BN1 batch stats per channel d ----------------
// grid = 16 blocks (one per d), 256 threads
__global__ void kB(const float* __restrict__ g1, const float* __restrict__ b1) {
    const int d = blockIdx.x, tid = threadIdx.x;
    float s = 0.f, s2 = 0.f;
    for (int b = 0; b < B_; b++) {
        const float* row = g_Y + (b * D_ + d) * M_;
        for (int m = tid; m < M_; m += 256) {
            float v = row[m];
            s += v; s2 += v * v;
        }
    }
    // intra-warp reduce
    for (int o = 16; o; o >>= 1) {
        s  += __shfl_xor_sync(~0u, s,  o);
        s2 += __shfl_xor_sync(~0u, s2, o);
    }
    __shared__ float sh1[8], sh2[8];
    int wid = tid >> 5, lane = tid & 31;
    if (!lane) { sh1[wid] = s; sh2[wid] = s2; }
    __syncthreads();
    if (tid == 0) {
        s = 0.f; s2 = 0.f;
        for (int wv = 0; wv < 8; wv++) { s += sh1[wv]; s2 += sh2[wv]; }
        const float inv = 1.0f / (float)(B_ * M_);
        float mu  = s * inv;
        float var = s2 * inv - mu * mu;
        float sc  = g1[d] * rsqrtf(var + EPS);
        g_bnS[d] = sc;
        g_bnB[d] = fmaf(-mu, sc, b1[d]);
    }
}

// ---------------- kC: BN+ReLU (on the fly) -> covariance pool --------------
// grid = 32 blocks (one per batch), 256 threads
__global__ void kC() {
    const int b = blockIdx.x, tid = threadIdx.x;
    __shared__ float sS[D_], sB[D_], rmean[D_];
    if (tid < D_) { sS[tid] = g_bnS[tid]; sB[tid] = g_bnB[tid]; }
    __syncthreads();

    // per-row spatial mean of relu(bn(y)) : one warp per 2 rows
    int wid = tid >> 5, lane = tid & 31;
    for (int d = wid; d < D_; d += 8) {
        const float* row = g_Y + (b * D_ + d) * M_;
        float sc = sS[d], bs = sB[d];
        float s = 0.f;
        for (int m = lane; m < M_; m += 32)
            s += fmaxf(fmaf(row[m], sc, bs), 0.f);
        for (int o = 16; o; o >>= 1) s += __shfl_xor_sync(~0u, s, o);
        if (!lane) rmean[d] = s * (1.0f / (float)M_);
    }
    __syncthreads();

    // cov[i][j] = E[y_i y_j] - mu_i mu_j   (136 unique pairs)
    if (tid < 136) {
        int i = 0, rem = tid;
        while (rem >= D_ - i) { rem -= D_ - i; i++; }
        int j = i + rem;
        const float4* ri = reinterpret_cast<const float4*>(g_Y + (b * D_ + i) * M_);
        const float4* rj = reinterpret_cast<const float4*>(g_Y + (b * D_ + j) * M_);
        float si = sS[i], bi = sB[i], sj = sS[j], bj = sB[j];
        float acc = 0.f;
#pragma unroll 4
        for (int m = 0; m < M_ / 4; m++) {
            float4 a = ri[m], c = rj[m];
            float a0 = fmaxf(fmaf(a.x, si, bi), 0.f);
            float a1 = fmaxf(fmaf(a.y, si, bi), 0.f);
            float a2 = fmaxf(fmaf(a.z, si, bi), 0.f);
            float a3 = fmaxf(fmaf(a.w, si, bi), 0.f);
            float c0 = fmaxf(fmaf(c.x, sj, bj), 0.f);
            float c1 = fmaxf(fmaf(c.y, sj, bj), 0.f);
            float c2 = fmaxf(fmaf(c.z, sj, bj), 0.f);
            float c3 = fmaxf(fmaf(c.w, sj, bj), 0.f);
            acc += a0 * c0 + a1 * c1 + a2 * c2 + a3 * c3;
        }
        float cv = acc * (1.0f / (float)M_) - rmean[i] * rmean[j];
        g_cov[(b * D_ + i) * D_ + j] = cv;
        if (i != j) g_cov[(b * D_ + j) * D_ + i] = cv;
    }
}

// ---------------- kD: row-BN + grouped row-conv -> r[B,64] -----------------
// 1 block, 512 threads (16 warps: one per cov row for stats)
__global__ void kD(const float* __restrict__ g2, const float* __restrict__ b2,
                   const float* __restrict__ w_row) {
    __shared__ float sc[B_ * D_ * D_];     // 8192 floats = 32KB
    __shared__ float mu2[D_], rst[D_];
    const int tid = threadIdx.x;
    for (int i = tid; i < B_ * D_ * D_; i += 512) sc[i] = g_cov[i];
    __syncthreads();

    int wid = tid >> 5, lane = tid & 31;
    {   // per-row-i stats over (b, j): 512 values, warp wid owns row i=wid
        int i = wid;
        float s = 0.f, s2 = 0.f;
        int base = (lane * D_ + i) * D_;   // lane = batch index
        for (int j = 0; j < D_; j++) {
            float v = sc[base + j];
            s += v; s2 += v * v;
        }
        for (int o = 16; o; o >>= 1) {
            s  += __shfl_xor_sync(~0u, s,  o);
            s2 += __shfl_xor_sync(~0u, s2, o);
        }
        if (!lane) {
            float m = s * (1.0f / 512.0f);
            float var = s2 * (1.0f / 512.0f) - m * m;
            mu2[i] = m;
            rst[i] = rsqrtf(var + EPS);
        }
    }
    __syncthreads();

    // r[b, g*4+j] = sum_h w_row[(g*4+j)*16 + h] * z[b,g,h]
    for (int t = tid; t < B_ * 64; t += 512) {
        int b = t >> 6, o = t & 63, g = o >> 2;
        float mg = mu2[g];
        float rg = rst[g] * g2[g];
        float bg = b2[g];
        const float* wr = w_row + o * D_;
        const float* cz = &sc[(b * D_ + g) * D_];
        float acc = 0.f;
#pragma unroll
        for (int h = 0; h < D_; h++) {
            float z = fmaf(cz[h] - mg, rg, bg);
            acc = fmaf(wr[h], z, acc);
        }
        g_r[t] = acc;
    }
}

// ---------------- kE: FC (2048x64) + sigmoid -> out[B,C] -------------------
// grid = 32*8 blocks, 256 threads; each thread one output channel
__global__ void kE(const float* __restrict__ w_fc, float* __restrict__ out) {
    __shared__ float rs[64];
    const int b = blockIdx.x >> 3, seg = blockIdx.x & 7, tid = threadIdx.x;
    if (tid < 64) rs[tid] = g_r[b * 64 + tid];
    __syncthreads();
    const int o = seg * 256 + tid;
    const float4* wp = reinterpret_cast<const float4*>(w_fc + (size_t)o * 64);
    float acc = 0.f;
#pragma unroll
    for (int q = 0; q < 16; q++) {
        float4 wv = wp[q];
        acc += wv.x * rs[4 * q] + wv.y * rs[4 * q + 1]
             + wv.z * rs[4 * q + 2] + wv.w * rs[4 * q + 3];
    }
    out[b * C_ + o] = 1.0f / (1.0f + __expf(-acc));
}

// ---------------- launch ----------------
extern "C" void kernel_launch(void* const* d_in, const int* in_sizes, int n_in,
                              void* d_out, int out_size) {
    const float* x      = (const float*)d_in[0];
    const float* w_conv = (const float*)d_in[1];
    const float* g1     = (const float*)d_in[2];
    const float* b1     = (const float*)d_in[3];
    const float* g2     = (const float*)d_in[4];
    const float* b2     = (const float*)d_in[5];
    const float* w_row  = (const float*)d_in[6];
    const float* w_fc   = (const float*)d_in[7];
    float* out = (float*)d_out;

    kZ<<<(B_ * D_ * M_ + 511) / 512, 512>>>();
    kA<<<B_ * NCHUNK, 416>>>(x, w_conv);
    kB<<<D_, 256>>>(g1, b1);
    kC<<<B_, 256>>>();
    kD<<<1, 512>>>(g2, b2, w_row);
    kE<<<B_ * 8, 256>>>(w_fc, out);
}

// round 4
// speedup vs baseline: 1.3313x; 1.3313x over previous
#include <cuda_runtime.h>

// Problem constants
#define B_   32
#define C_   2048
#define D_   16
#define M_   784           // 28*28
#define CHUNK  256
#define NCHUNK (C_/CHUNK)  // 8
#define EPS  1e-5f

// ---------------- scratch (device globals; no allocations) ----------------
__device__ float g_Y[B_ * D_ * M_];     // conv output, pre-BN  (1.6 MB)
__device__ float g_rs1[B_ * D_];        // per-(b,d) row sum
__device__ float g_rs2[B_ * D_];        // per-(b,d) row sum of squares
__device__ float g_cov[B_ * D_ * D_];   // covariance pool

// packed f32x2 FMA (Blackwell): acc = a*b + acc, lanewise on 2 packed floats
__device__ __forceinline__ void fma2(unsigned long long &acc,
                                     unsigned long long a,
                                     unsigned long long b) {
    asm("fma.rn.f32x2 %0, %1, %2, %0;" : "+l"(acc) : "l"(a), "l"(b));
}

// ---------------- kZ: zero the Y accumulator ----------------
__global__ void kZ() {
    int i = blockIdx.x * blockDim.x + threadIdx.x;
    if (i < B_ * D_ * M_) g_Y[i] = 0.0f;
}

// ---------------- kA: y[b,d,m] += sum_{c in chunk} w[d,c] * x[b,c,m] -------
// grid = B_*NCHUNK blocks, 416 threads (392 compute lanes, 2 m each)
// c-loop unrolled by 8 with front-batched LDG.64 -> MLP=8 per thread.
__global__ __launch_bounds__(416) void kA(const float* __restrict__ x,
                                          const float* __restrict__ w) {
    __shared__ __align__(16) float2 sw[CHUNK][D_];  // (w,w) duplicated pairs, 32KB

    const int b   = blockIdx.x / NCHUNK;
    const int ch  = blockIdx.x % NCHUNK;
    const int c0  = ch * CHUNK;
    const int tid = threadIdx.x;

    for (int i = tid; i < CHUNK * D_; i += 416) {
        int c = i >> 4, d = i & 15;
        float wv = w[d * C_ + c0 + c];
        sw[c][d] = make_float2(wv, wv);
    }
    __syncthreads();

    if (tid >= 392) return;             // 392*2 = 784 m positions
    const int m0 = tid * 2;
    const float* xb = x + ((size_t)b * C_ + c0) * M_ + m0;

    unsigned long long acc[D_];
#pragma unroll
    for (int d = 0; d < D_; d++) acc[d] = 0ull;

    for (int c = 0; c < CHUNK; c += 8) {
        unsigned long long xv[8];
#pragma unroll
        for (int u = 0; u < 8; u++)
            xv[u] = *reinterpret_cast<const unsigned long long*>(
                        xb + (size_t)(c + u) * M_);
#pragma unroll
        for (int u = 0; u < 8; u++) {
            const ulonglong2* wp =
                reinterpret_cast<const ulonglong2*>(&sw[c + u][0]);
#pragma unroll
            for (int q = 0; q < 8; q++) {
                ulonglong2 w2 = wp[q];
                fma2(acc[2 * q],     xv[u], w2.x);
                fma2(acc[2 * q + 1], xv[u], w2.y);
            }
        }
    }

    float* yb = g_Y + (b * D_) * M_ + m0;
#pragma unroll
    for (int d = 0; d < D_; d++) {
        float lo = __uint_as_float((unsigned int)(acc[d] & 0xffffffffull));
        float hi = __uint_as_float((unsigned int)(acc[d] >> 32));
        atomicAdd(yb + d * M_,     lo);
        atomicAdd(yb + d * M_ + 1, hi);
    }
}

// ---------------- kB: per-(b,d) row sums ----------------
// grid = 512 blocks (b*16+d), 128 threads
__global__ void kB(void) {
    const int bid = blockIdx.x, tid = threadIdx.x;
    const float4* row = reinterpret_cast<const float4*>(g_Y + bid * M_);
    float s = 0.f, s2 = 0.f;
    for (int m = tid; m < M_ / 4; m += 128) {
        float4 v = row[m];
        s  += v.x + v.y + v.z + v.w;
        s2 += v.x * v.x + v.y * v.y + v.z * v.z + v.w * v.w;
    }
    for (int o = 16; o; o >>= 1) {
        s  += __shfl_xor_sync(~0u, s,  o);
        s2 += __shfl_xor_sync(~0u, s2, o);
    }
    __shared__ float sh1[4], sh2[4];
    int wid = tid >> 5, lane = tid & 31;
    if (!lane) { sh1[wid] = s; sh2[wid] = s2; }
    __syncthreads();
    if (tid == 0) {
        g_rs1[bid] = sh1[0] + sh1[1] + sh1[2] + sh1[3];
        g_rs2[bid] = sh2[0] + sh2[1] + sh2[2] + sh2[3];
    }
}

// ---------------- kC: BN+ReLU -> shared-staged covariance pool -------------
// grid = 32 blocks (one per batch), 544 threads (17 warps)
// 4 partial-summers per (i,j) pair; Y staged in shared in two 392-m halves.
__global__ __launch_bounds__(544) void kC(const float* __restrict__ g1,
                                          const float* __restrict__ b1) {
    __shared__ float sS[D_], sB[D_], rmean[D_];
    __shared__ __align__(16) float ys[D_][392];   // 24.5 KB

    const int b = blockIdx.x, tid = threadIdx.x;
    const int wid = tid >> 5, lane = tid & 31;

    // BN1 scale/bias from global row sums (redundant per block, trivial)
    if (wid < D_) {
        const int d = wid;
        float s  = g_rs1[lane * D_ + d];
        float s2 = g_rs2[lane * D_ + d];
        for (int o = 16; o; o >>= 1) {
            s  += __shfl_xor_sync(~0u, s,  o);
            s2 += __shfl_xor_sync(~0u, s2, o);
        }
        if (!lane) {
            const float inv = 1.0f / (float)(B_ * M_);
            float mu  = s * inv;
            float var = s2 * inv - mu * mu;
            float sc  = g1[d] * rsqrtf(var + EPS);
            sS[d] = sc;
            sB[d] = fmaf(-mu, sc, b1[d]);
        }
    }

    const int p = tid >> 2, q = tid & 3;   // pair index (0..135), quarter
    int pi = 0, rem = p;
    while (rem >= D_ - pi) { rem -= D_ - pi; pi++; }
    const int pj = pi + rem;

    float pacc = 0.f;
    for (int half = 0; half < 2; half++) {
        const int mbase = half * 392;
        __syncthreads();   // (a) sS/sB ready (first iter); (b) ys consumed (second)
        // stage 16 rows x 392 m with BN+ReLU, float4
        for (int idx = tid; idx < D_ * 98; idx += 544) {
            int d = idx / 98, mm = idx % 98;
            float4 v = *reinterpret_cast<const float4*>(
                g_Y + (b * D_ + d) * M_ + mbase + mm * 4);
            float sc = sS[d], bs = sB[d];
            v.x = fmaxf(fmaf(v.x, sc, bs), 0.f);
            v.y = fmaxf(fmaf(v.y, sc, bs), 0.f);
            v.z = fmaxf(fmaf(v.z, sc, bs), 0.f);
            v.w = fmaxf(fmaf(v.w, sc, bs), 0.f);
            *reinterpret_cast<float4*>(&ys[d][mm * 4]) = v;
        }
        __syncthreads();
        // row means: warps 0..15, one row each
        if (wid < D_) {
            float s = 0.f;
            for (int m = lane; m < 392; m += 32) s += ys[wid][m];
            for (int o = 16; o; o >>= 1) s += __shfl_xor_sync(~0u, s, o);
            if (!lane) {
                float part = s * (1.0f / (float)M_);
                rmean[wid] = half ? (rmean[wid] + part) : part;
            }
        }
        // pair products over this thread's 98-m stripe (float2)
        {
            const float2* ri = reinterpret_cast<const float2*>(&ys[pi][q * 98]);
            const float2* rj = reinterpret_cast<const float2*>(&ys[pj][q * 98]);
#pragma unroll 7
            for (int m = 0; m < 49; m++) {
                float2 a = ri[m], c = rj[m];
                pacc = fmaf(a.x, c.x, pacc);
                pacc = fmaf(a.y, c.y, pacc);
            }
        }
    }
    __syncthreads();   // rmean final & visible

    // reduce the 4 quarter-partials (lanes p*4+q, aligned groups of 4)
    pacc += __shfl_xor_sync(~0u, pacc, 1);
    pacc += __shfl_xor_sync(~0u, pacc, 2);
    if (q == 0) {
        float cv = pacc * (1.0f / (float)M_) - rmean[pi] * rmean[pj];
        g_cov[(b * D_ + pi) * D_ + pj] = cv;
        if (pi != pj) g_cov[(b * D_ + pj) * D_ + pi] = cv;
    }
}

// ---------------- kE: row-BN + grouped row-conv + FC + sigmoid -------------
// grid = 32*8 blocks, 256 threads; thread -> one output channel
__global__ __launch_bounds__(256) void kE(const float* __restrict__ g2,
                                          const float* __restrict__ b2,
                                          const float* __restrict__ w_row,
                                          const float* __restrict__ w_fc,
                                          float* __restrict__ out) {
    __shared__ float mu2[D_], rst[D_], rs[64];
    const int b = blockIdx.x >> 3, seg = blockIdx.x & 7, tid = threadIdx.x;
    const int wid = tid >> 5, lane = tid & 31;

    // row-BN stats over (batch, j) per row i: 8 warps x 2 rows (L2-hot cov)
#pragma unroll
    for (int i = wid; i < D_; i += 8) {
        const float4* cp = reinterpret_cast<const float4*>(
            g_cov + (lane * D_ + i) * D_);
        float s = 0.f, s2 = 0.f;
#pragma unroll
        for (int t = 0; t < 4; t++) {
            float4 v = cp[t];
            s  += v.x + v.y + v.z + v.w;
            s2 += v.x * v.x + v.y * v.y + v.z * v.z + v.w * v.w;
        }
        for (int o = 16; o; o >>= 1) {
            s  += __shfl_xor_sync(~0u, s,  o);
            s2 += __shfl_xor_sync(~0u, s2, o);
        }
        if (!lane) {
            float m   = s * (1.0f / 512.0f);
            float var = s2 * (1.0f / 512.0f) - m * m;
            mu2[i] = m;
            rst[i] = rsqrtf(var + EPS);
        }
    }
    __syncthreads();

    // grouped row conv for this block's batch
    if (tid < 64) {
        const int o = tid, g = o >> 2;
        float mg = mu2[g];
        float rg = rst[g] * g2[g];
        float bg = b2[g];
        const float* wr = w_row + o * D_;
        const float* cz = g_cov + (b * D_ + g) * D_;
        float a = 0.f;
#pragma unroll
        for (int h = 0; h < D_; h++) {
            float z = fmaf(cz[h] - mg, rg, bg);
            a = fmaf(wr[h], z, a);
        }
        rs[o] = a;
    }
    __syncthreads();

    const int o = seg * 256 + tid;
    const float4* wp = reinterpret_cast<const float4*>(w_fc + (size_t)o * 64);
    float acc = 0.f;
#pragma unroll
    for (int t = 0; t < 16; t++) {
        float4 wv = wp[t];
        acc += wv.x * rs[4 * t] + wv.y * rs[4 * t + 1]
             + wv.z * rs[4 * t + 2] + wv.w * rs[4 * t + 3];
    }
    out[b * C_ + o] = 1.0f / (1.0f + __expf(-acc));
}

// ---------------- launch ----------------
extern "C" void kernel_launch(void* const* d_in, const int* in_sizes, int n_in,
                              void* d_out, int out_size) {
    const float* x      = (const float*)d_in[0];
    const float* w_conv = (const float*)d_in[1];
    const float* g1     = (const float*)d_in[2];
    const float* b1     = (const float*)d_in[3];
    const float* g2     = (const float*)d_in[4];
    const float* b2     = (const float*)d_in[5];
    const float* w_row  = (const float*)d_in[6];
    const float* w_fc   = (const float*)d_in[7];
    float* out = (float*)d_out;

    kZ<<<(B_ * D_ * M_ + 511) / 512, 512>>>();
    kA<<<B_ * NCHUNK, 416>>>(x, w_conv);
    kB<<<B_ * D_, 128>>>();
    kC<<<B_, 544>>>(g1, b1);
    kE<<<B_ * 8, 256>>>(g2, b2, w_row, w_fc, out);
}

// round 6
// speedup vs baseline: 1.5623x; 1.1735x over previous
#include <cuda_runtime.h>

// Problem constants
#define B_   32
#define C_   2048
#define D_   16
#define M_   784           // 28*28
#define CHUNK  256
#define NCHUNK (C_/CHUNK)  // 8
#define NPAIR 136
#define EPS  1e-5f

// ---------------- scratch (device globals; no allocations) ----------------
__device__ float g_Yp[NCHUNK * B_ * D_ * M_]; // per-chunk conv partials (12.8 MB)
__device__ float g_rs1[B_ * D_];              // per-(b,d) row sum
__device__ float g_rs2[B_ * D_];              // per-(b,d) row sum of squares
__device__ float g_S[B_ * NPAIR];             // pair product sums (atomic)
__device__ float g_mean[B_ * D_];             // per-(b,d) spatial sums (atomic)

// packed f32x2 FMA (Blackwell)
__device__ __forceinline__ void fma2(unsigned long long &acc,
                                     unsigned long long a,
                                     unsigned long long b) {
    asm("fma.rn.f32x2 %0, %1, %2, %0;" : "+l"(acc) : "l"(a), "l"(b));
}

// ---------------- kA: partial y[b,d,m] = sum_{c in chunk} w[d,c]*x[b,c,m] --
// grid = B_*NCHUNK, 224 threads (196 compute lanes, 4 m each)
__global__ __launch_bounds__(224) void kA(const float* __restrict__ x,
                                          const float* __restrict__ w) {
    __shared__ __align__(16) float2 sw[CHUNK][D_];  // (w,w) pairs, 32KB

    const int b   = blockIdx.x / NCHUNK;
    const int ch  = blockIdx.x % NCHUNK;
    const int c0  = ch * CHUNK;
    const int tid = threadIdx.x;

    for (int i = tid; i < CHUNK * D_; i += 224) {
        int c = i >> 4, d = i & 15;
        float wv = w[d * C_ + c0 + c];
        sw[c][d] = make_float2(wv, wv);
    }
    __syncthreads();

    if (tid >= 196) return;             // 196*4 = 784 m positions
    const int m0 = tid * 4;
    const float* xb = x + ((size_t)b * C_ + c0) * M_ + m0;

    unsigned long long acc[D_][2];
#pragma unroll
    for (int d = 0; d < D_; d++) { acc[d][0] = 0ull; acc[d][1] = 0ull; }

    for (int c = 0; c < CHUNK; c += 4) {
        ulonglong2 xv[4];
#pragma unroll
        for (int u = 0; u < 4; u++)
            xv[u] = *reinterpret_cast<const ulonglong2*>(
                        xb + (size_t)(c + u) * M_);
#pragma unroll
        for (int u = 0; u < 4; u++) {
            const ulonglong2* wp =
                reinterpret_cast<const ulonglong2*>(&sw[c + u][0]);
#pragma unroll
            for (int q = 0; q < 8; q++) {
                ulonglong2 w2 = wp[q];
                fma2(acc[2 * q][0],     xv[u].x, w2.x);
                fma2(acc[2 * q][1],     xv[u].y, w2.x);
                fma2(acc[2 * q + 1][0], xv[u].x, w2.y);
                fma2(acc[2 * q + 1][1], xv[u].y, w2.y);
            }
        }
    }

    float* yb = g_Yp + ((size_t)(ch * B_ + b) * D_) * M_ + m0;
#pragma unroll
    for (int d = 0; d < D_; d++) {
        ulonglong2 v; v.x = acc[d][0]; v.y = acc[d][1];
        *reinterpret_cast<ulonglong2*>(yb + d * M_) = v;
    }
}

// ---------------- kB: per-(b,d) row sums over summed partials --------------
// grid = 512 blocks (b*16+d), 128 threads. Block 0 also zeroes g_S/g_mean.
__global__ void kB(void) {
    const int bid = blockIdx.x, tid = threadIdx.x;

    if (bid == 0) {
        for (int i = tid; i < B_ * NPAIR; i += 128) g_S[i] = 0.f;
        for (int i = tid; i < B_ * D_;   i += 128) g_mean[i] = 0.f;
    }

    const float4* base = reinterpret_cast<const float4*>(g_Yp) + bid * (M_ / 4);
    const int pstride = B_ * D_ * (M_ / 4);
    float s = 0.f, s2 = 0.f;
    for (int m = tid; m < M_ / 4; m += 128) {
        float4 v = base[m];
#pragma unroll
        for (int ch = 1; ch < NCHUNK; ch++) {
            float4 p = base[ch * pstride + m];
            v.x += p.x; v.y += p.y; v.z += p.z; v.w += p.w;
        }
        s  += v.x + v.y + v.z + v.w;
        s2 += v.x * v.x + v.y * v.y + v.z * v.z + v.w * v.w;
    }
    for (int o = 16; o; o >>= 1) {
        s  += __shfl_xor_sync(~0u, s,  o);
        s2 += __shfl_xor_sync(~0u, s2, o);
    }
    __shared__ float sh1[4], sh2[4];
    int wid = tid >> 5, lane = tid & 31;
    if (!lane) { sh1[wid] = s; sh2[wid] = s2; }
    __syncthreads();
    if (tid == 0) {
        g_rs1[bid] = sh1[0] + sh1[1] + sh1[2] + sh1[3];
        g_rs2[bid] = sh2[0] + sh2[1] + sh2[2] + sh2[3];
    }
}

// ---------------- kC: BN+ReLU -> partial pair sums (quarter of m) ----------
// grid = 32*4 blocks (b, m-quarter of 196), 288 threads
__global__ __launch_bounds__(288) void kC(const float* __restrict__ g1,
                                          const float* __restrict__ b1) {
    __shared__ float sS[D_], sB[D_];
    __shared__ __align__(16) float ys[D_][196];   // 12.25 KB

    const int b = blockIdx.x >> 2, qtr = blockIdx.x & 3;
    const int tid = threadIdx.x;
    const int wid = tid >> 5, lane = tid & 31;

    // BN1 coefficients (redundant per block; reads 1KB of L2-hot sums)
    if (tid < D_) {
        float s = 0.f, s2 = 0.f;
#pragma unroll
        for (int bb = 0; bb < B_; bb++) {
            s  += g_rs1[bb * D_ + tid];
            s2 += g_rs2[bb * D_ + tid];
        }
        const float inv = 1.0f / (float)(B_ * M_);
        float mu  = s * inv;
        float var = s2 * inv - mu * mu;
        float sc  = g1[tid] * rsqrtf(var + EPS);
        sS[tid] = sc;
        sB[tid] = fmaf(-mu, sc, b1[tid]);
    }
    __syncthreads();

    // stage: ys[d][0..195] = relu(bn(sum_ch partials)) for m-quarter
    const int m4base = qtr * (196 / 4);    // float4 offset within row
    const int pstride = B_ * D_ * (M_ / 4);
    for (int idx = tid; idx < D_ * 49; idx += 288) {
        int d = idx / 49, m4 = idx % 49;
        const float4* base = reinterpret_cast<const float4*>(g_Yp)
                             + (b * D_ + d) * (M_ / 4) + m4base + m4;
        float4 v = base[0];
#pragma unroll
        for (int ch = 1; ch < NCHUNK; ch++) {
            float4 p = base[ch * pstride];
            v.x += p.x; v.y += p.y; v.z += p.z; v.w += p.w;
        }
        float sc = sS[d], bs = sB[d];
        v.x = fmaxf(fmaf(v.x, sc, bs), 0.f);
        v.y = fmaxf(fmaf(v.y, sc, bs), 0.f);
        v.z = fmaxf(fmaf(v.z, sc, bs), 0.f);
        v.w = fmaxf(fmaf(v.w, sc, bs), 0.f);
        *reinterpret_cast<float4*>(&ys[d][m4 * 4]) = v;
    }
    __syncthreads();

    // partial row sums
    for (int r = wid; r < D_; r += 9) {
        float s = 0.f;
        for (int m = lane; m < 196; m += 32) s += ys[r][m];
        for (int o = 16; o; o >>= 1) s += __shfl_xor_sync(~0u, s, o);
        if (!lane) atomicAdd(&g_mean[b * D_ + r], s);
    }

    // pair partial products: thread t -> pair t>>1, half t&1 (98 m)
    {
        int p = tid >> 1;
        bool valid = (p < NPAIR);
        int pc = valid ? p : NPAIR - 1;
        int pi = 0, rem = pc;
        while (rem >= D_ - pi) { rem -= D_ - pi; pi++; }
        int pj = pi + rem;
        int h = tid & 1;
        const float2* ri = reinterpret_cast<const float2*>(&ys[pi][h * 98]);
        const float2* rj = reinterpret_cast<const float2*>(&ys[pj][h * 98]);
        float pacc = 0.f;
#pragma unroll 7
        for (int m = 0; m < 49; m++) {
            float2 a = ri[m], c = rj[m];
            pacc = fmaf(a.x, c.x, pacc);
            pacc = fmaf(a.y, c.y, pacc);
        }
        pacc += __shfl_xor_sync(~0u, pacc, 1);
        if (valid && h == 0) atomicAdd(&g_S[b * NPAIR + p], pacc);
    }
}

// ---------------- kE: finalize cov + row-BN + row-conv + FC + sigmoid ------
// grid = 32*8 blocks, 256 threads
__global__ __launch_bounds__(256) void kE(const float* __restrict__ g2,
                                          const float* __restrict__ b2,
                                          const float* __restrict__ w_row,
                                          const float* __restrict__ w_fc,
                                          float* __restrict__ out) {
    __shared__ float zc[D_ * D_ * 33];     // [i][j][b'] padded, 33.8 KB
    __shared__ float smu[B_ * D_];
    __shared__ float mu2[D_], rst[D_], rs[64];

    const int b = blockIdx.x >> 3, seg = blockIdx.x & 7, tid = threadIdx.x;
    const int wid = tid >> 5, lane = tid & 31;

    // spatial means
    for (int i = tid; i < B_ * D_; i += 256)
        smu[i] = g_mean[i] * (1.0f / (float)M_);
    __syncthreads();

    // finalize cov: task t -> pair p=t>>5, batch b'=t&31
    for (int t = tid; t < NPAIR * B_; t += 256) {
        int p = t >> 5, bb = t & 31;
        int pi = 0, rem = p;
        while (rem >= D_ - pi) { rem -= D_ - pi; pi++; }
        int pj = pi + rem;
        float cv = g_S[bb * NPAIR + p] * (1.0f / (float)M_)
                 - smu[bb * D_ + pi] * smu[bb * D_ + pj];
        zc[(pi * D_ + pj) * 33 + bb] = cv;
        if (pi != pj) zc[(pj * D_ + pi) * 33 + bb] = cv;
    }
    __syncthreads();

    // row-BN stats per row i over (b', j): 512 values
#pragma unroll
    for (int i = wid; i < D_; i += 8) {
        float s = 0.f, s2 = 0.f;
#pragma unroll
        for (int j = 0; j < D_; j++) {
            float v = zc[(i * D_ + j) * 33 + lane];
            s += v; s2 += v * v;
        }
        for (int o = 16; o; o >>= 1) {
            s  += __shfl_xor_sync(~0u, s,  o);
            s2 += __shfl_xor_sync(~0u, s2, o);
        }
        if (!lane) {
            float m   = s * (1.0f / 512.0f);
            float var = s2 * (1.0f / 512.0f) - m * m;
            mu2[i] = m;
            rst[i] = rsqrtf(var + EPS);
        }
    }
    __syncthreads();

    // grouped row conv for this block's batch
    if (tid < 64) {
        const int o = tid, g = o >> 2;
        float mg = mu2[g];
        float rg = rst[g] * g2[g];
        float bg = b2[g];
        const float* wr = w_row + o * D_;
        float a = 0.f;
#pragma unroll
        for (int h = 0; h < D_; h++) {
            float z = fmaf(zc[(g * D_ + h) * 33 + b] - mg, rg, bg);
            a = fmaf(wr[h], z, a);
        }
        rs[o] = a;
    }
    __syncthreads();

    const int o = seg * 256 + tid;
    const float4* wp = reinterpret_cast<const float4*>(w_fc + (size_t)o * 64);
    float acc = 0.f;
#pragma unroll
    for (int t = 0; t < 16; t++) {
        float4 wv = wp[t];
        acc += wv.x * rs[4 * t] + wv.y * rs[4 * t + 1]
             + wv.z * rs[4 * t + 2] + wv.w * rs[4 * t + 3];
    }
    out[b * C_ + o] = 1.0f / (1.0f + __expf(-acc));
}

// ---------------- launch ----------------
extern "C" void kernel_launch(void* const* d_in, const int* in_sizes, int n_in,
                              void* d_out, int out_size) {
    const float* x      = (const float*)d_in[0];
    const float* w_conv = (const float*)d_in[1];
    const float* g1     = (const float*)d_in[2];
    const float* b1     = (const float*)d_in[3];
    const float* g2     = (const float*)d_in[4];
    const float* b2     = (const float*)d_in[5];
    const float* w_row  = (const float*)d_in[6];
    const float* w_fc   = (const float*)d_in[7];
    float* out = (float*)d_out;

    kA<<<B_ * NCHUNK, 224>>>(x, w_conv);
    kB<<<B_ * D_, 128>>>();
    kC<<<B_ * 4, 288>>>(g1, b1);
    kE<<<B_ * 8, 256>>>(g2, b2, w_row, w_fc, out);
}